// round 1
// baseline (speedup 1.0000x reference)
#include <cuda_runtime.h>

#define NN      64
#define NTYPES  4
#define NDESC   8
#define KMAX    8
#define RC      8.0f
#define PI_F    3.14159265358979323846f

__device__ __forceinline__ float fsqrt_approx(float x) {
    float y; asm("sqrt.approx.f32 %0, %1;" : "=f"(y) : "f"(x)); return y;
}
__device__ __forceinline__ float fcos_approx(float x) {
    float y; asm("cos.approx.f32 %0, %1;" : "=f"(y) : "f"(x)); return y;
}

// 8 lanes per atom, 4 atoms per warp, 8 warps per block -> 32 atoms/block.
// Per-type Chebyshev accumulation G[4][8], halving-butterfly reduction over the
// 8-lane group, per-atom 4x8->8 matvec against shared c_table, coalesced store.
__global__ __launch_bounds__(256) void radial_desc_kernel(
    const int*   __restrict__ types,
    const float* __restrict__ pos,
    const int*   __restrict__ nbr,
    const float* __restrict__ offs,
    const float* __restrict__ ctab,
    float*       __restrict__ out,
    int n_atoms)
{
    __shared__ float c_sh[NTYPES * NTYPES * NDESC * KMAX];  // 1024 floats = 4 KB
    for (int i = threadIdx.x; i < NTYPES * NTYPES * NDESC * KMAX; i += blockDim.x)
        c_sh[i] = ctab[i];
    __syncthreads();

    const int lane = threadIdx.x & 31;
    const int warp = threadIdx.x >> 5;
    const int s    = lane & 7;    // lane within 8-lane group
    const int g    = lane >> 3;   // group (atom slot) within warp

    const int atom = (blockIdx.x * 8 + warp) * 4 + g;
    const bool ok  = (atom < n_atoms);
    const int a    = ok ? atom : 0;

    const float pax = pos[a * 3 + 0];
    const float pay = pos[a * 3 + 1];
    const float paz = pos[a * 3 + 2];
    const int   ti  = types[a];

    float G[4][8];
    #pragma unroll
    for (int t = 0; t < 4; t++)
        #pragma unroll
        for (int k = 0; k < 8; k++)
            G[t][k] = 0.0f;

    const int*   nb = nbr  + (long)a * NN;
    const float* ob = offs + (long)a * NN * 3;

    #pragma unroll 4
    for (int e = 0; e < 8; e++) {
        const int j = e * 8 + s;                 // each lane: 8 edges, group covers all 64
        const int n = nb[j];
        const bool valid = (n >= 0) && ok;
        const int ns = valid ? n : 0;

        const float ox = ob[j * 3 + 0];
        const float oy = ob[j * 3 + 1];
        const float oz = ob[j * 3 + 2];

        const float dx = pos[ns * 3 + 0] + ox - pax;
        const float dy = pos[ns * 3 + 1] + oy - pay;
        const float dz = pos[ns * 3 + 2] + oz - paz;
        const int   tj = types[ns];

        const float r2 = dx * dx + dy * dy + dz * dz;
        const float r  = fsqrt_approx(r2);

        // h = 0.5 * fc ; fc = (r<RC) ? 0.5*cos(pi*r/RC)+0.5 : 0. Invalid edges fold to h=0.
        const float h = (valid && (r < RC))
                      ? (0.25f * fcos_approx(r * (PI_F / RC)) + 0.25f)
                      : 0.0f;

        const float u  = r * (1.0f / RC) - 1.0f;
        const float x  = 2.0f * u * u - 1.0f;
        const float tw = x + x;

        float T[8];
        T[1] = x;
        T[2] = tw * x - 1.0f;
        #pragma unroll
        for (int k = 3; k < 8; k++) T[k] = tw * T[k - 1] - T[k - 2];

        // Per-type accumulation. T0 == 1 so G[t][0] doubles as the sum of wh.
        #pragma unroll
        for (int t = 0; t < 4; t++) {
            const float wh = (tj == t) ? h : 0.0f;
            G[t][0] += wh;
            #pragma unroll
            for (int k = 1; k < 8; k++) G[t][k] += wh * T[k];
        }
    }

    // ---- halving-butterfly reduction of 32 values over the 8-lane group ----
    // flatten v[i] = G[i>>3][i&7]
    float* v = &G[0][0];
    const bool hi4 = (s & 4) != 0;
    const bool hi2 = (s & 2) != 0;
    const bool hi1 = (s & 1) != 0;

    float v1[16];
    #pragma unroll
    for (int i = 0; i < 16; i++) {
        const float send = hi4 ? v[i] : v[i + 16];
        const float recv = __shfl_xor_sync(0xffffffffu, send, 4);
        v1[i] = (hi4 ? v[i + 16] : v[i]) + recv;
    }
    float v2[8];
    #pragma unroll
    for (int i = 0; i < 8; i++) {
        const float send = hi2 ? v1[i] : v1[i + 8];
        const float recv = __shfl_xor_sync(0xffffffffu, send, 2);
        v2[i] = (hi2 ? v1[i + 8] : v1[i]) + recv;
    }
    float v3[4];
    #pragma unroll
    for (int i = 0; i < 4; i++) {
        const float send = hi1 ? v2[i] : v2[i + 4];
        const float recv = __shfl_xor_sync(0xffffffffu, send, 1);
        v3[i] = (hi1 ? v2[i + 4] : v2[i]) + recv;
    }
    // lane s now holds totals for t = ((s&4)>>1)|((s&2)>>1), k = (s&1)*4 + k'
    const int tl = ((s & 4) >> 1) | ((s & 2) >> 1);

    // F[t][k] = G[t][k] + G[t][0] (folds the (T_k + 1) constant term; k=0 -> 2*G[t][0])
    const float g0 = __shfl_sync(0xffffffffu, v3[0], lane & ~1);
    const float F0 = v3[0] + g0;
    const float F1 = v3[1] + g0;
    const float F2 = v3[2] + g0;
    const float F3 = v3[3] + g0;

    // matvec: each lane contributes its 4 (t,k) entries to all 8 descriptors
    const float4* c4p = reinterpret_cast<const float4*>(c_sh);
    const int base = ((ti * 4 + tl) * 8) * 2 + (s & 1);
    float p[8];
    #pragma unroll
    for (int d = 0; d < 8; d++) {
        const float4 c = c4p[base + d * 2];
        p[d] = c.x * F0 + c.y * F1 + c.z * F2 + c.w * F3;
    }

    // reduce p[0..7] over the 8-lane group; value d lands on lane s == d
    float q[4];
    #pragma unroll
    for (int i = 0; i < 4; i++) {
        const float send = hi4 ? p[i] : p[i + 4];
        const float recv = __shfl_xor_sync(0xffffffffu, send, 4);
        q[i] = (hi4 ? p[i + 4] : p[i]) + recv;
    }
    float rr[2];
    #pragma unroll
    for (int i = 0; i < 2; i++) {
        const float send = hi2 ? q[i] : q[i + 2];
        const float recv = __shfl_xor_sync(0xffffffffu, send, 2);
        rr[i] = (hi2 ? q[i + 2] : q[i]) + recv;
    }
    {
        const float send = hi1 ? rr[0] : rr[1];
        const float recv = __shfl_xor_sync(0xffffffffu, send, 1);
        const float o = (hi1 ? rr[1] : rr[0]) + recv;
        if (ok) out[(long)atom * 8 + s] = o;   // warp store = 128B contiguous
    }
}

extern "C" void kernel_launch(void* const* d_in, const int* in_sizes, int n_in,
                              void* d_out, int out_size) {
    const int*   types = (const int*)  d_in[0];
    const float* pos   = (const float*)d_in[1];
    const int*   nbr   = (const int*)  d_in[2];
    const float* offs  = (const float*)d_in[3];
    const float* ctab  = (const float*)d_in[4];
    float* out = (float*)d_out;

    const int n_atoms = in_sizes[0];
    const int atoms_per_block = 32;               // 8 warps * 4 atoms
    const int grid = (n_atoms + atoms_per_block - 1) / atoms_per_block;

    radial_desc_kernel<<<grid, 256>>>(types, pos, nbr, offs, ctab, out, n_atoms);
}

// round 2
// speedup vs baseline: 1.2600x; 1.2600x over previous
#include <cuda_runtime.h>

#define NN      64
#define NTYPES  4
#define NDESC   8
#define KMAX    8
#define RC      8.0f
#define PI_F    3.14159265358979323846f
#define MAX_ATOMS 32768

// packed[i] = (pos.x, pos.y, pos.z, bitcast(type))
__device__ float4 g_packed[MAX_ATOMS];

__device__ __forceinline__ float fsqrt_approx(float x) {
    float y; asm("sqrt.approx.f32 %0, %1;" : "=f"(y) : "f"(x)); return y;
}
__device__ __forceinline__ float fcos_approx(float x) {
    float y; asm("cos.approx.f32 %0, %1;" : "=f"(y) : "f"(x)); return y;
}

__global__ void pack_kernel(const int* __restrict__ types,
                            const float* __restrict__ pos, int n)
{
    int i = blockIdx.x * blockDim.x + threadIdx.x;
    if (i < n) {
        float4 p;
        p.x = pos[i * 3 + 0];
        p.y = pos[i * 3 + 1];
        p.z = pos[i * 3 + 2];
        p.w = __int_as_float(types[i]);
        g_packed[i] = p;
    }
}

// 8 lanes per atom, 4 atoms per warp, 8 warps per block -> 32 atoms/block.
// Lane s owns contiguous edges [s*8, s*8+8): nbr = 2x int4, offs = 6x float4.
// Neighbor pos+type fetched as ONE LDG.128 gather per edge.
__global__ __launch_bounds__(256) void radial_desc_kernel(
    const int*   __restrict__ nbr,
    const float* __restrict__ offs,
    const float* __restrict__ ctab,
    float*       __restrict__ out,
    int n_atoms)
{
    __shared__ float c_sh[NTYPES * NTYPES * NDESC * KMAX];  // 4 KB
    for (int i = threadIdx.x; i < NTYPES * NTYPES * NDESC * KMAX; i += blockDim.x)
        c_sh[i] = ctab[i];
    __syncthreads();

    const int lane = threadIdx.x & 31;
    const int warp = threadIdx.x >> 5;
    const int s    = lane & 7;    // lane within 8-lane group
    const int g    = lane >> 3;   // atom slot within warp

    const int atom = (blockIdx.x * 8 + warp) * 4 + g;
    const bool ok  = (atom < n_atoms);
    const int a    = ok ? atom : 0;

    const float4 pa = g_packed[a];
    const int    ti = __float_as_int(pa.w);

    float G[4][8];
    #pragma unroll
    for (int t = 0; t < 4; t++)
        #pragma unroll
        for (int k = 0; k < 8; k++)
            G[t][k] = 0.0f;

    const int4*   nb4 = reinterpret_cast<const int4*>(nbr)   + (long)a * 16 + s * 2;
    const float4* ob4 = reinterpret_cast<const float4*>(offs) + (long)a * 48 + s * 6;

    #pragma unroll
    for (int half = 0; half < 2; half++) {
        const int4 nv = nb4[half];
        const int nidx[4] = { nv.x, nv.y, nv.z, nv.w };

        const float4 f0 = ob4[half * 3 + 0];
        const float4 f1 = ob4[half * 3 + 1];
        const float4 f2 = ob4[half * 3 + 2];
        const float ox[4] = { f0.x, f0.w, f1.z, f2.y };
        const float oy[4] = { f0.y, f1.x, f1.w, f2.z };
        const float oz[4] = { f0.z, f1.y, f2.x, f2.w };

        // issue all 4 gathers up-front for MLP
        float4 P[4];
        bool   vld[4];
        #pragma unroll
        for (int e = 0; e < 4; e++) {
            const int n = nidx[e];
            vld[e] = (n >= 0) && ok;
            P[e] = g_packed[vld[e] ? n : 0];
        }

        #pragma unroll
        for (int e = 0; e < 4; e++) {
            const float dx = P[e].x + ox[e] - pa.x;
            const float dy = P[e].y + oy[e] - pa.y;
            const float dz = P[e].z + oz[e] - pa.z;
            const int   tj = __float_as_int(P[e].w);

            const float r2 = dx * dx + dy * dy + dz * dz;
            const float r  = fsqrt_approx(r2);

            const float h = (vld[e] && (r < RC))
                          ? (0.25f * fcos_approx(r * (PI_F / RC)) + 0.25f)
                          : 0.0f;

            const float u  = r * (1.0f / RC) - 1.0f;
            const float x  = 2.0f * u * u - 1.0f;
            const float tw = x + x;

            float T[8];
            T[1] = x;
            T[2] = tw * x - 1.0f;
            #pragma unroll
            for (int k = 3; k < 8; k++) T[k] = tw * T[k - 1] - T[k - 2];

            #pragma unroll
            for (int t = 0; t < 4; t++) {
                const float wh = (tj == t) ? h : 0.0f;
                G[t][0] += wh;                       // T0 == 1
                #pragma unroll
                for (int k = 1; k < 8; k++) G[t][k] += wh * T[k];
            }
        }
    }

    // ---- halving-butterfly reduction of 32 values over the 8-lane group ----
    float* v = &G[0][0];
    const bool hi4 = (s & 4) != 0;
    const bool hi2 = (s & 2) != 0;
    const bool hi1 = (s & 1) != 0;

    float v1[16];
    #pragma unroll
    for (int i = 0; i < 16; i++) {
        const float send = hi4 ? v[i] : v[i + 16];
        const float recv = __shfl_xor_sync(0xffffffffu, send, 4);
        v1[i] = (hi4 ? v[i + 16] : v[i]) + recv;
    }
    float v2[8];
    #pragma unroll
    for (int i = 0; i < 8; i++) {
        const float send = hi2 ? v1[i] : v1[i + 8];
        const float recv = __shfl_xor_sync(0xffffffffu, send, 2);
        v2[i] = (hi2 ? v1[i + 8] : v1[i]) + recv;
    }
    float v3[4];
    #pragma unroll
    for (int i = 0; i < 4; i++) {
        const float send = hi1 ? v2[i] : v2[i + 4];
        const float recv = __shfl_xor_sync(0xffffffffu, send, 1);
        v3[i] = (hi1 ? v2[i + 4] : v2[i]) + recv;
    }
    // lane s holds totals for t = ((s&4)>>1)|((s&2)>>1), k = (s&1)*4 + k'
    const int tl = ((s & 4) >> 1) | ((s & 2) >> 1);

    // F[t][k] = G[t][k] + G[t][0]  (folds the (T_k + 1) term; k=0 -> 2*G[t][0])
    const float g0 = __shfl_sync(0xffffffffu, v3[0], lane & ~1);
    const float F0 = v3[0] + g0;
    const float F1 = v3[1] + g0;
    const float F2 = v3[2] + g0;
    const float F3 = v3[3] + g0;

    const float4* c4p = reinterpret_cast<const float4*>(c_sh);
    const int base = ((ti * 4 + tl) * 8) * 2 + (s & 1);
    float p[8];
    #pragma unroll
    for (int d = 0; d < 8; d++) {
        const float4 c = c4p[base + d * 2];
        p[d] = c.x * F0 + c.y * F1 + c.z * F2 + c.w * F3;
    }

    float q[4];
    #pragma unroll
    for (int i = 0; i < 4; i++) {
        const float send = hi4 ? p[i] : p[i + 4];
        const float recv = __shfl_xor_sync(0xffffffffu, send, 4);
        q[i] = (hi4 ? p[i + 4] : p[i]) + recv;
    }
    float rr[2];
    #pragma unroll
    for (int i = 0; i < 2; i++) {
        const float send = hi2 ? q[i] : q[i + 2];
        const float recv = __shfl_xor_sync(0xffffffffu, send, 2);
        rr[i] = (hi2 ? q[i + 2] : q[i]) + recv;
    }
    {
        const float send = hi1 ? rr[0] : rr[1];
        const float recv = __shfl_xor_sync(0xffffffffu, send, 1);
        const float o = (hi1 ? rr[1] : rr[0]) + recv;
        if (ok) out[(long)atom * 8 + s] = o;   // coalesced 128B warp store
    }
}

extern "C" void kernel_launch(void* const* d_in, const int* in_sizes, int n_in,
                              void* d_out, int out_size) {
    const int*   types = (const int*)  d_in[0];
    const float* pos   = (const float*)d_in[1];
    const int*   nbr   = (const int*)  d_in[2];
    const float* offs  = (const float*)d_in[3];
    const float* ctab  = (const float*)d_in[4];
    float* out = (float*)d_out;

    int n_atoms = in_sizes[0];
    if (n_atoms > MAX_ATOMS) n_atoms = MAX_ATOMS;

    pack_kernel<<<(n_atoms + 255) / 256, 256>>>(types, pos, n_atoms);

    const int atoms_per_block = 32;               // 8 warps * 4 atoms
    const int grid = (n_atoms + atoms_per_block - 1) / atoms_per_block;
    radial_desc_kernel<<<grid, 256>>>(nbr, offs, ctab, out, n_atoms);
}